// round 2
// baseline (speedup 1.0000x reference)
#include <cuda_runtime.h>
#include <cuda_bf16.h>
#include <math.h>

#define NN 40000
#define EE 640000
#define DD 128
#define HH 8
#define HD 16
#define D2 256

// ---------------- scratch (static __device__ allowed by harness rules) ------
__device__ float g_Q[NN * DD];
__device__ float g_K[NN * DD];
__device__ float g_V[NN * DD];
__device__ float g_wV[NN * DD];
__device__ float g_z[NN * HH];
__device__ float g_h1[NN * DD];
__device__ float g_tmp_h[NN * DD];
__device__ float g_hid_h[NN * D2];
__device__ float g_pe[(size_t)EE * DD];     // becomes score / e_out in place
__device__ float g_e1[(size_t)EE * DD];
__device__ float g_tmp_e[(size_t)EE * DD];
__device__ float g_hid_e[(size_t)EE * D2];

// ---------------- mma.sync m16n8k16 bf16 wrapper ----------------------------
__device__ __forceinline__ void mma16816(float* c, const unsigned* a, const unsigned* b) {
    asm volatile(
        "mma.sync.aligned.m16n8k16.row.col.f32.bf16.bf16.f32 "
        "{%0,%1,%2,%3}, {%4,%5,%6,%7}, {%8,%9}, {%0,%1,%2,%3};"
        : "+f"(c[0]), "+f"(c[1]), "+f"(c[2]), "+f"(c[3])
        : "r"(a[0]), "r"(a[1]), "r"(a[2]), "r"(a[3]), "r"(b[0]), "r"(b[1]));
}

// ---------------- GEMM: C[M,Ncol] = A[M,K] @ B[K,Ncol] (+bias, relu) --------
// Tensor-core bf16 3-term hi/lo split (fp32-equivalent accuracy).
// Block tile 128x128, BK=32, 256 threads = 8 warps (4x2), warp tile 32x64.
// Smem: A and B^T both stored [128 rows][32 k] bf16, row stride 40 (pad 8)
// -> conflict-free fragment loads for m16n8k16 row.col layout.
#define SA 40
template <bool BIAS, bool RELU>
__global__ __launch_bounds__(256, 2) void gemm_tc(const float* __restrict__ A,
                                                  const float* __restrict__ B,
                                                  const float* __restrict__ bias,
                                                  float* __restrict__ C,
                                                  int M, int K, int Ncol) {
    __shared__ __nv_bfloat16 Ah[128 * SA];
    __shared__ __nv_bfloat16 Al[128 * SA];
    __shared__ __nv_bfloat16 Bh[128 * SA];
    __shared__ __nv_bfloat16 Bl[128 * SA];

    const int tid = threadIdx.x;
    const int lane = tid & 31;
    const int wid = tid >> 5;
    const int warp_m = wid & 3;   // 0..3 -> 32-row slab
    const int warp_n = wid >> 2;  // 0..1 -> 64-col slab
    const int bm = blockIdx.y * 128;
    const int bn = blockIdx.x * 128;
    const int g = lane >> 2;      // groupID 0..7
    const int tg = lane & 3;      // thread-in-group 0..3

    float c[2][8][4];
#pragma unroll
    for (int mt = 0; mt < 2; mt++)
#pragma unroll
        for (int nt = 0; nt < 8; nt++)
#pragma unroll
            for (int j = 0; j < 4; j++) c[mt][nt][j] = 0.f;

    for (int k0 = 0; k0 < K; k0 += 32) {
        // ---- A tile: 128 rows x 32 k, convert fp32 -> (hi,lo) bf16 ----
#pragma unroll
        for (int it = 0; it < 4; it++) {
            int idx = tid + it * 256;         // 0..1023 float4 slots
            int r = idx >> 3;                 // 0..127
            int kq = (idx & 7) << 2;          // 0..28
            int grow = bm + r;
            float4 v = make_float4(0.f, 0.f, 0.f, 0.f);
            if (grow < M) v = *(const float4*)&A[(size_t)grow * K + k0 + kq];
            float x[4] = {v.x, v.y, v.z, v.w};
#pragma unroll
            for (int j = 0; j < 4; j++) {
                __nv_bfloat16 hi = __float2bfloat16_rn(x[j]);
                __nv_bfloat16 lo = __float2bfloat16_rn(x[j] - __bfloat162float(hi));
                Ah[r * SA + kq + j] = hi;
                Al[r * SA + kq + j] = lo;
            }
        }
        // ---- B tile: 32 k-rows x 128 n-cols -> transposed Bt[n][k] ----
#pragma unroll
        for (int it = 0; it < 4; it++) {
            int idx = tid + it * 256;
            int kr = idx >> 5;                // 0..31
            int nq = (idx & 31) << 2;         // 0..124
            float4 v = *(const float4*)&B[(size_t)(k0 + kr) * Ncol + bn + nq];
            float x[4] = {v.x, v.y, v.z, v.w};
#pragma unroll
            for (int j = 0; j < 4; j++) {
                __nv_bfloat16 hi = __float2bfloat16_rn(x[j]);
                __nv_bfloat16 lo = __float2bfloat16_rn(x[j] - __bfloat162float(hi));
                Bh[(nq + j) * SA + kr] = hi;
                Bl[(nq + j) * SA + kr] = lo;
            }
        }
        __syncthreads();

#pragma unroll
        for (int ks = 0; ks < 32; ks += 16) {
            unsigned ah[2][4], al[2][4];
#pragma unroll
            for (int mt = 0; mt < 2; mt++) {
                int row = warp_m * 32 + mt * 16 + g;
                int o0 = row * SA + ks + tg * 2;
                int o8 = o0 + 8 * SA;
                ah[mt][0] = *(const unsigned*)&Ah[o0];
                ah[mt][1] = *(const unsigned*)&Ah[o8];
                ah[mt][2] = *(const unsigned*)&Ah[o0 + 8];
                ah[mt][3] = *(const unsigned*)&Ah[o8 + 8];
                al[mt][0] = *(const unsigned*)&Al[o0];
                al[mt][1] = *(const unsigned*)&Al[o8];
                al[mt][2] = *(const unsigned*)&Al[o0 + 8];
                al[mt][3] = *(const unsigned*)&Al[o8 + 8];
            }
#pragma unroll
            for (int nt = 0; nt < 8; nt++) {
                int n = warp_n * 64 + nt * 8 + g;
                int bo = n * SA + ks + tg * 2;
                unsigned bh[2], bl[2];
                bh[0] = *(const unsigned*)&Bh[bo];
                bh[1] = *(const unsigned*)&Bh[bo + 8];
                bl[0] = *(const unsigned*)&Bl[bo];
                bl[1] = *(const unsigned*)&Bl[bo + 8];
#pragma unroll
                for (int mt = 0; mt < 2; mt++) {
                    mma16816(c[mt][nt], ah[mt], bh);
                    mma16816(c[mt][nt], ah[mt], bl);
                    mma16816(c[mt][nt], al[mt], bh);
                }
            }
        }
        __syncthreads();
    }

    // ---- epilogue ----
#pragma unroll
    for (int mt = 0; mt < 2; mt++) {
#pragma unroll
        for (int nt = 0; nt < 8; nt++) {
            int r0 = bm + warp_m * 32 + mt * 16 + g;
            int r1 = r0 + 8;
            int cb = bn + warp_n * 64 + nt * 8 + tg * 2;
            float v0 = c[mt][nt][0], v1 = c[mt][nt][1];
            float v2 = c[mt][nt][2], v3 = c[mt][nt][3];
            if (BIAS) {
                float b0 = bias[cb], b1 = bias[cb + 1];
                v0 += b0; v1 += b1; v2 += b0; v3 += b1;
            }
            if (RELU) {
                v0 = fmaxf(v0, 0.f); v1 = fmaxf(v1, 0.f);
                v2 = fmaxf(v2, 0.f); v3 = fmaxf(v3, 0.f);
            }
            if (r0 < M) *(float2*)&C[(size_t)r0 * Ncol + cb] = make_float2(v0, v1);
            if (r1 < M) *(float2*)&C[(size_t)r1 * Ncol + cb] = make_float2(v2, v3);
        }
    }
}

// ---------------- zero wV / z ----------------------------------------------
__global__ void zero_kernel() {
    int i = blockIdx.x * 256 + threadIdx.x;
    if (i < NN * DD) g_wV[i] = 0.f;
    int j = i - NN * DD;
    if (j >= 0 && j < NN * HH) g_z[j] = 0.f;
}

// ---------------- edge attention: score (in place on g_pe), exp, scatter ----
// one warp per edge; lane handles 4 consecutive elements; head = lane/4
__global__ void edge_attn(const int* __restrict__ src, const int* __restrict__ dst) {
    int e = blockIdx.x * 8 + (threadIdx.x >> 5);
    if (e >= EE) return;
    int lane = threadIdx.x & 31;
    int s = src[e];
    int d = dst[e];
    int col = lane * 4;
    size_t eb = (size_t)e * DD + col;

    float4 k4 = *(const float4*)&g_K[(size_t)s * DD + col];
    float4 q4 = *(const float4*)&g_Q[(size_t)d * DD + col];
    float4 p4 = *(const float4*)&g_pe[eb];
    float4 v4 = *(const float4*)&g_V[(size_t)s * DD + col];

    const float isq = 0.25f;  // 1/sqrt(HD=16)
    float4 sc;
    sc.x = k4.x * q4.x * isq * p4.x;
    sc.y = k4.y * q4.y * isq * p4.y;
    sc.z = k4.z * q4.z * isq * p4.z;
    sc.w = k4.w * q4.w * isq * p4.w;
    *(float4*)&g_pe[eb] = sc;  // e_out (pre-exp score), in place

    float part = sc.x + sc.y + sc.z + sc.w;
    part += __shfl_xor_sync(0xffffffffu, part, 1);
    part += __shfl_xor_sync(0xffffffffu, part, 2);  // head-sum in each 4-lane group

    float se = expf(fminf(fmaxf(part, -5.f), 5.f));

    atomicAdd(&g_wV[(size_t)d * DD + col + 0], v4.x * se);
    atomicAdd(&g_wV[(size_t)d * DD + col + 1], v4.y * se);
    atomicAdd(&g_wV[(size_t)d * DD + col + 2], v4.z * se);
    atomicAdd(&g_wV[(size_t)d * DD + col + 3], v4.w * se);
    if ((lane & 3) == 0) atomicAdd(&g_z[d * HH + (lane >> 2)], se);
}

// ---------------- h_attn = wV / (z + 1e-6), in place on g_wV ----------------
__global__ void finalize_attn() {
    int i = blockIdx.x * 256 + threadIdx.x;  // i < NN*DD
    int n = i >> 7;
    int d = i & 127;
    g_wV[i] = g_wV[i] / (g_z[n * HH + (d >> 4)] + 1e-6f);
}

// ---------------- LN(base + proj + bias) * gamma + beta, warp per row -------
__global__ void ln_kernel(const float* __restrict__ base, const float* __restrict__ proj,
                          const float* __restrict__ bias, const float* __restrict__ gamma,
                          const float* __restrict__ beta, float* __restrict__ out,
                          int rows) {
    int row = blockIdx.x * 8 + (threadIdx.x >> 5);
    if (row >= rows) return;
    int lane = threadIdx.x & 31;
    int col = lane * 4;
    size_t off = (size_t)row * DD + col;

    float4 x = *(const float4*)&base[off];
    float4 p = *(const float4*)&proj[off];
    float4 bb = *(const float4*)&bias[col];
    float v0 = x.x + p.x + bb.x;
    float v1 = x.y + p.y + bb.y;
    float v2 = x.z + p.z + bb.z;
    float v3 = x.w + p.w + bb.w;

    float s = v0 + v1 + v2 + v3;
    float sq = v0 * v0 + v1 * v1 + v2 * v2 + v3 * v3;
#pragma unroll
    for (int o = 16; o > 0; o >>= 1) {
        s += __shfl_xor_sync(0xffffffffu, s, o);
        sq += __shfl_xor_sync(0xffffffffu, sq, o);
    }
    float mean = s * (1.f / 128.f);
    float var = sq * (1.f / 128.f) - mean * mean;
    float r = rsqrtf(var + 1e-5f);

    float4 g = *(const float4*)&gamma[col];
    float4 be = *(const float4*)&beta[col];
    float4 o4;
    o4.x = (v0 - mean) * r * g.x + be.x;
    o4.y = (v1 - mean) * r * g.y + be.y;
    o4.z = (v2 - mean) * r * g.z + be.z;
    o4.w = (v3 - mean) * r * g.w + be.w;
    *(float4*)&out[off] = o4;
}

// ---------------- launch ----------------------------------------------------
extern "C" void kernel_launch(void* const* d_in, const int* in_sizes, int n_in,
                              void* d_out, int out_size) {
    const float* h = (const float*)d_in[0];
    const float* e = (const float*)d_in[1];
    const int* src = (const int*)d_in[2];
    const int* dst = (const int*)d_in[3];
    const float* WQ = (const float*)d_in[4];
    const float* WK = (const float*)d_in[5];
    const float* WV = (const float*)d_in[6];
    const float* We = (const float*)d_in[7];
    const float* WOh = (const float*)d_in[8];
    const float* bOh = (const float*)d_in[9];
    const float* WOe = (const float*)d_in[10];
    const float* bOe = (const float*)d_in[11];
    const float* g1h = (const float*)d_in[12];
    const float* b1h = (const float*)d_in[13];
    const float* g1e = (const float*)d_in[14];
    const float* b1e = (const float*)d_in[15];
    const float* Wh1 = (const float*)d_in[16];
    const float* bh1 = (const float*)d_in[17];
    const float* Wh2 = (const float*)d_in[18];
    const float* bh2 = (const float*)d_in[19];
    const float* We1 = (const float*)d_in[20];
    const float* be1 = (const float*)d_in[21];
    const float* We2 = (const float*)d_in[22];
    const float* be2 = (const float*)d_in[23];
    const float* g2h = (const float*)d_in[24];
    const float* b2h = (const float*)d_in[25];
    const float* g2e = (const float*)d_in[26];
    const float* b2e = (const float*)d_in[27];

    float* out_h = (float*)d_out;
    float* out_e = out_h + (size_t)NN * DD;

    float *pQ, *pK, *pV, *pwV, *ph1, *pth, *phh, *ppe, *pe1, *pte, *phe;
    cudaGetSymbolAddress((void**)&pQ, g_Q);
    cudaGetSymbolAddress((void**)&pK, g_K);
    cudaGetSymbolAddress((void**)&pV, g_V);
    cudaGetSymbolAddress((void**)&pwV, g_wV);
    cudaGetSymbolAddress((void**)&ph1, g_h1);
    cudaGetSymbolAddress((void**)&pth, g_tmp_h);
    cudaGetSymbolAddress((void**)&phh, g_hid_h);
    cudaGetSymbolAddress((void**)&ppe, g_pe);
    cudaGetSymbolAddress((void**)&pe1, g_e1);
    cudaGetSymbolAddress((void**)&pte, g_tmp_e);
    cudaGetSymbolAddress((void**)&phe, g_hid_e);

    const int MB_N = (NN + 127) / 128;  // 313
    const int MB_E = EE / 128;          // 5000
    const int LNB_N = (NN + 7) / 8;     // 5000
    const int LNB_E = EE / 8;           // 80000

    zero_kernel<<<(NN * DD + NN * HH + 255) / 256, 256>>>();

    // QKV + edge projection
    gemm_tc<false, false><<<dim3(1, MB_N), 256>>>(h, WQ, nullptr, pQ, NN, DD, DD);
    gemm_tc<false, false><<<dim3(1, MB_N), 256>>>(h, WK, nullptr, pK, NN, DD, DD);
    gemm_tc<false, false><<<dim3(1, MB_N), 256>>>(h, WV, nullptr, pV, NN, DD, DD);
    gemm_tc<false, false><<<dim3(1, MB_E), 256>>>(e, We, nullptr, ppe, EE, DD, DD);

    // attention over edges
    edge_attn<<<EE / 8, 256>>>(src, dst);
    finalize_attn<<<NN * DD / 256, 256>>>();

    // output projections + LN
    gemm_tc<false, false><<<dim3(1, MB_N), 256>>>(pwV, WOh, nullptr, pth, NN, DD, DD);
    ln_kernel<<<LNB_N, 256>>>(h, pth, bOh, g1h, b1h, ph1, NN);
    gemm_tc<false, false><<<dim3(1, MB_E), 256>>>(ppe, WOe, nullptr, pte, EE, DD, DD);
    ln_kernel<<<LNB_E, 256>>>(e, pte, bOe, g1e, b1e, pe1, EE);

    // node FFN
    gemm_tc<true, true><<<dim3(2, MB_N), 256>>>(ph1, Wh1, bh1, phh, NN, DD, D2);
    gemm_tc<false, false><<<dim3(1, MB_N), 256>>>(phh, Wh2, nullptr, pth, NN, D2, DD);
    ln_kernel<<<LNB_N, 256>>>(ph1, pth, bh2, g2h, b2h, out_h, NN);

    // edge FFN
    gemm_tc<true, true><<<dim3(2, MB_E), 256>>>(pe1, We1, be1, phe, EE, DD, D2);
    gemm_tc<false, false><<<dim3(1, MB_E), 256>>>(phe, We2, nullptr, pte, EE, D2, DD);
    ln_kernel<<<LNB_E, 256>>>(pe1, pte, be2, g2e, b2e, out_e, EE);
}

// round 5
// speedup vs baseline: 1.1396x; 1.1396x over previous
#include <cuda_runtime.h>
#include <cuda_bf16.h>
#include <math.h>

#define NN 40000
#define EE 640000
#define DD 128
#define HH 8
#define HD 16
#define D2 256

// ---------------- scratch (static __device__ allowed by harness rules) ------
__device__ float g_Q[NN * DD];
__device__ float g_K[NN * DD];
__device__ float g_V[NN * DD];
__device__ float g_wV[NN * DD];
__device__ float g_z[NN * HH];
__device__ float g_h1[NN * DD];
__device__ float g_hid_h[NN * D2];
__device__ float g_pe[(size_t)EE * DD];     // becomes score / e_out in place
__device__ float g_e1[(size_t)EE * DD];
__device__ float g_hid_e[(size_t)EE * D2];

// ---------------- mma.sync m16n8k16 bf16 + ldmatrix wrappers ----------------
__device__ __forceinline__ void mma16816(float* c, const unsigned* a, const unsigned* b) {
    asm volatile(
        "mma.sync.aligned.m16n8k16.row.col.f32.bf16.bf16.f32 "
        "{%0,%1,%2,%3}, {%4,%5,%6,%7}, {%8,%9}, {%0,%1,%2,%3};"
        : "+f"(c[0]), "+f"(c[1]), "+f"(c[2]), "+f"(c[3])
        : "r"(a[0]), "r"(a[1]), "r"(a[2]), "r"(a[3]), "r"(b[0]), "r"(b[1]));
}

__device__ __forceinline__ void ldsm4(unsigned& r0, unsigned& r1, unsigned& r2, unsigned& r3,
                                      const __nv_bfloat16* p) {
    unsigned addr = (unsigned)__cvta_generic_to_shared(p);
    asm volatile("ldmatrix.sync.aligned.m8n8.x4.shared.b16 {%0,%1,%2,%3}, [%4];"
                 : "=r"(r0), "=r"(r1), "=r"(r2), "=r"(r3)
                 : "r"(addr));
}

__device__ __forceinline__ void red_add_v4(float* p, float a, float b, float c, float d) {
    asm volatile("red.global.add.v4.f32 [%0], {%1,%2,%3,%4};"
                 :: "l"(p), "f"(a), "f"(b), "f"(c), "f"(d)
                 : "memory");
}

// ---------------- GEMM: C[M,Ncol] = A[M,K] @ B[K,Ncol] ----------------------
// Tensor-core bf16 3-term hi/lo split (fp32-equivalent accuracy).
// Block tile 128x128, BK=32, 256 threads = 8 warps (4x2), warp tile 32x64.
// ldmatrix.x4 fragment loads; SA=40 padding -> conflict-free LDSM.
// LN=true fuses: out = LN(base + C + bias) * gamma + beta  (requires Ncol==128,
// gridDim.x==1). BIAS/RELU are ignored when LN is set.
#define SA 40
template <bool BIAS, bool RELU, bool LN>
__global__ __launch_bounds__(256, 2) void gemm_tc(const float* __restrict__ A,
                                                  const float* __restrict__ B,
                                                  const float* __restrict__ bias,
                                                  float* __restrict__ C,
                                                  int M, int K, int Ncol,
                                                  const float* __restrict__ base,
                                                  const float* __restrict__ gamma,
                                                  const float* __restrict__ beta) {
    __shared__ __nv_bfloat16 Ah[128 * SA];
    __shared__ __nv_bfloat16 Al[128 * SA];
    __shared__ __nv_bfloat16 Bh[128 * SA];
    __shared__ __nv_bfloat16 Bl[128 * SA];
    __shared__ float rsum[128];
    __shared__ float rsq[128];

    const int tid = threadIdx.x;
    const int lane = tid & 31;
    const int wid = tid >> 5;
    const int warp_m = wid & 3;   // 0..3 -> 32-row slab
    const int warp_n = wid >> 2;  // 0..1 -> 64-col slab
    const int bm = blockIdx.y * 128;
    const int bn = blockIdx.x * 128;
    const int g = lane >> 2;      // groupID 0..7
    const int tg = lane & 3;      // thread-in-group 0..3

    // ldmatrix per-lane source rows/cols
    const int arow = warp_m * 32 + (lane & 15);          // + mt*16
    const int akoff = (lane >> 4) << 3;                  // + ks
    const int brow = warp_n * 64 + ((lane >> 4) & 1) * 8 + (lane & 7);  // + j*16
    const int bkoff = ((lane >> 3) & 1) << 3;            // + ks

    float c[2][8][4];
#pragma unroll
    for (int mt = 0; mt < 2; mt++)
#pragma unroll
        for (int nt = 0; nt < 8; nt++)
#pragma unroll
            for (int j = 0; j < 4; j++) c[mt][nt][j] = 0.f;

    for (int k0 = 0; k0 < K; k0 += 32) {
        // ---- A tile: 128 rows x 32 k, convert fp32 -> (hi,lo) bf16 ----
#pragma unroll
        for (int it = 0; it < 4; it++) {
            int idx = tid + it * 256;         // 0..1023 float4 slots
            int r = idx >> 3;                 // 0..127
            int kq = (idx & 7) << 2;          // 0..28
            int grow = bm + r;
            float4 v = make_float4(0.f, 0.f, 0.f, 0.f);
            if (grow < M) v = *(const float4*)&A[(size_t)grow * K + k0 + kq];
            float x[4] = {v.x, v.y, v.z, v.w};
#pragma unroll
            for (int j = 0; j < 4; j++) {
                __nv_bfloat16 hi = __float2bfloat16_rn(x[j]);
                __nv_bfloat16 lo = __float2bfloat16_rn(x[j] - __bfloat162float(hi));
                Ah[r * SA + kq + j] = hi;
                Al[r * SA + kq + j] = lo;
            }
        }
        // ---- B tile: 32 k-rows x 128 n-cols -> transposed Bt[n][k] ----
#pragma unroll
        for (int it = 0; it < 4; it++) {
            int idx = tid + it * 256;
            int kr = idx >> 5;                // 0..31
            int nq = (idx & 31) << 2;         // 0..124
            float4 v = *(const float4*)&B[(size_t)(k0 + kr) * Ncol + bn + nq];
            float x[4] = {v.x, v.y, v.z, v.w};
#pragma unroll
            for (int j = 0; j < 4; j++) {
                __nv_bfloat16 hi = __float2bfloat16_rn(x[j]);
                __nv_bfloat16 lo = __float2bfloat16_rn(x[j] - __bfloat162float(hi));
                Bh[(nq + j) * SA + kr] = hi;
                Bl[(nq + j) * SA + kr] = lo;
            }
        }
        __syncthreads();

#pragma unroll
        for (int ks = 0; ks < 32; ks += 16) {
            unsigned ah[2][4], al[2][4], bb[8][2];
#pragma unroll
            for (int mt = 0; mt < 2; mt++) {
                ldsm4(ah[mt][0], ah[mt][1], ah[mt][2], ah[mt][3],
                      &Ah[(arow + mt * 16) * SA + ks + akoff]);
                ldsm4(al[mt][0], al[mt][1], al[mt][2], al[mt][3],
                      &Al[(arow + mt * 16) * SA + ks + akoff]);
            }
            // B hi fragments: 4 x4-ldmatrix load all 8 n-tiles
#pragma unroll
            for (int j = 0; j < 4; j++)
                ldsm4(bb[2 * j][0], bb[2 * j][1], bb[2 * j + 1][0], bb[2 * j + 1][1],
                      &Bh[(brow + j * 16) * SA + ks + bkoff]);
#pragma unroll
            for (int nt = 0; nt < 8; nt++)
#pragma unroll
                for (int mt = 0; mt < 2; mt++) {
                    mma16816(c[mt][nt], ah[mt], bb[nt]);
                    mma16816(c[mt][nt], al[mt], bb[nt]);
                }
            // B lo fragments overwrite bb
#pragma unroll
            for (int j = 0; j < 4; j++)
                ldsm4(bb[2 * j][0], bb[2 * j][1], bb[2 * j + 1][0], bb[2 * j + 1][1],
                      &Bl[(brow + j * 16) * SA + ks + bkoff]);
#pragma unroll
            for (int nt = 0; nt < 8; nt++)
#pragma unroll
                for (int mt = 0; mt < 2; mt++) mma16816(c[mt][nt], ah[mt], bb[nt]);
        }
        __syncthreads();
    }

    if (LN) {
        // fused residual + bias + LayerNorm epilogue (Ncol==128, gridDim.x==1)
        if (tid < 128) {
            rsum[tid] = 0.f;
            rsq[tid] = 0.f;
        }
        __syncthreads();
        float p[2][2] = {{0.f, 0.f}, {0.f, 0.f}};
        float q[2][2] = {{0.f, 0.f}, {0.f, 0.f}};
#pragma unroll
        for (int mt = 0; mt < 2; mt++) {
            int r0g = bm + warp_m * 32 + mt * 16 + g;
            int r1g = r0g + 8;
#pragma unroll
            for (int nt = 0; nt < 8; nt++) {
                int cb = warp_n * 64 + nt * 8 + tg * 2;
                float b0 = bias[cb], b1 = bias[cb + 1];
                float2 ba0 = make_float2(0.f, 0.f), ba1 = make_float2(0.f, 0.f);
                if (r0g < M) ba0 = *(const float2*)&base[(size_t)r0g * 128 + cb];
                if (r1g < M) ba1 = *(const float2*)&base[(size_t)r1g * 128 + cb];
                float v0 = c[mt][nt][0] + b0 + ba0.x;
                float v1 = c[mt][nt][1] + b1 + ba0.y;
                float v2 = c[mt][nt][2] + b0 + ba1.x;
                float v3 = c[mt][nt][3] + b1 + ba1.y;
                c[mt][nt][0] = v0; c[mt][nt][1] = v1;
                c[mt][nt][2] = v2; c[mt][nt][3] = v3;
                p[mt][0] += v0 + v1; q[mt][0] += v0 * v0 + v1 * v1;
                p[mt][1] += v2 + v3; q[mt][1] += v2 * v2 + v3 * v3;
            }
        }
#pragma unroll
        for (int o = 1; o <= 2; o <<= 1) {
#pragma unroll
            for (int mt = 0; mt < 2; mt++)
#pragma unroll
                for (int r = 0; r < 2; r++) {
                    p[mt][r] += __shfl_xor_sync(0xffffffffu, p[mt][r], o);
                    q[mt][r] += __shfl_xor_sync(0xffffffffu, q[mt][r], o);
                }
        }
        if (tg == 0) {
#pragma unroll
            for (int mt = 0; mt < 2; mt++) {
                int rl = warp_m * 32 + mt * 16 + g;
                atomicAdd(&rsum[rl], p[mt][0]);
                atomicAdd(&rsq[rl], q[mt][0]);
                atomicAdd(&rsum[rl + 8], p[mt][1]);
                atomicAdd(&rsq[rl + 8], q[mt][1]);
            }
        }
        __syncthreads();
#pragma unroll
        for (int mt = 0; mt < 2; mt++) {
            int rl0 = warp_m * 32 + mt * 16 + g;
            int rl1 = rl0 + 8;
            int r0g = bm + rl0, r1g = bm + rl1;
            float m0 = rsum[rl0] * (1.f / 128.f);
            float m1 = rsum[rl1] * (1.f / 128.f);
            float rs0 = rsqrtf(rsq[rl0] * (1.f / 128.f) - m0 * m0 + 1e-5f);
            float rs1 = rsqrtf(rsq[rl1] * (1.f / 128.f) - m1 * m1 + 1e-5f);
#pragma unroll
            for (int nt = 0; nt < 8; nt++) {
                int cb = warp_n * 64 + nt * 8 + tg * 2;
                float2 ga = *(const float2*)&gamma[cb];
                float2 be = *(const float2*)&beta[cb];
                if (r0g < M) {
                    float2 o0;
                    o0.x = (c[mt][nt][0] - m0) * rs0 * ga.x + be.x;
                    o0.y = (c[mt][nt][1] - m0) * rs0 * ga.y + be.y;
                    *(float2*)&C[(size_t)r0g * 128 + cb] = o0;
                }
                if (r1g < M) {
                    float2 o1;
                    o1.x = (c[mt][nt][2] - m1) * rs1 * ga.x + be.x;
                    o1.y = (c[mt][nt][3] - m1) * rs1 * ga.y + be.y;
                    *(float2*)&C[(size_t)r1g * 128 + cb] = o1;
                }
            }
        }
    } else {
        // plain epilogue (+bias, +relu)
#pragma unroll
        for (int mt = 0; mt < 2; mt++) {
#pragma unroll
            for (int nt = 0; nt < 8; nt++) {
                int r0 = bm + warp_m * 32 + mt * 16 + g;
                int r1 = r0 + 8;
                int cb = bn + warp_n * 64 + nt * 8 + tg * 2;
                float v0 = c[mt][nt][0], v1 = c[mt][nt][1];
                float v2 = c[mt][nt][2], v3 = c[mt][nt][3];
                if (BIAS) {
                    float b0 = bias[cb], b1 = bias[cb + 1];
                    v0 += b0; v1 += b1; v2 += b0; v3 += b1;
                }
                if (RELU) {
                    v0 = fmaxf(v0, 0.f); v1 = fmaxf(v1, 0.f);
                    v2 = fmaxf(v2, 0.f); v3 = fmaxf(v3, 0.f);
                }
                if (r0 < M) *(float2*)&C[(size_t)r0 * Ncol + cb] = make_float2(v0, v1);
                if (r1 < M) *(float2*)&C[(size_t)r1 * Ncol + cb] = make_float2(v2, v3);
            }
        }
    }
}

// ---------------- zero wV / z ----------------------------------------------
__global__ void zero_kernel() {
    int i = blockIdx.x * 256 + threadIdx.x;
    if (i < NN * DD) g_wV[i] = 0.f;
    int j = i - NN * DD;
    if (j >= 0 && j < NN * HH) g_z[j] = 0.f;
}

// ---------------- edge attention: score (in place on g_pe), exp, scatter ----
// one warp per edge; lane handles 4 consecutive elements; head = lane/4
__global__ void edge_attn(const int* __restrict__ src, const int* __restrict__ dst) {
    int e = blockIdx.x * 8 + (threadIdx.x >> 5);
    if (e >= EE) return;
    int lane = threadIdx.x & 31;
    int s = src[e];
    int d = dst[e];
    int col = lane * 4;
    size_t eb = (size_t)e * DD + col;

    float4 k4 = *(const float4*)&g_K[(size_t)s * DD + col];
    float4 q4 = *(const float4*)&g_Q[(size_t)d * DD + col];
    float4 p4 = *(const float4*)&g_pe[eb];
    float4 v4 = *(const float4*)&g_V[(size_t)s * DD + col];

    const float isq = 0.25f;  // 1/sqrt(HD=16)
    float4 sc;
    sc.x = k4.x * q4.x * isq * p4.x;
    sc.y = k4.y * q4.y * isq * p4.y;
    sc.z = k4.z * q4.z * isq * p4.z;
    sc.w = k4.w * q4.w * isq * p4.w;
    *(float4*)&g_pe[eb] = sc;  // e_out (pre-exp score), in place

    float part = sc.x + sc.y + sc.z + sc.w;
    part += __shfl_xor_sync(0xffffffffu, part, 1);
    part += __shfl_xor_sync(0xffffffffu, part, 2);  // head-sum in each 4-lane group

    float se = expf(fminf(fmaxf(part, -5.f), 5.f));

    // vectorized non-returning reduction: 1 op instead of 4 scalar atomics
    red_add_v4(&g_wV[(size_t)d * DD + col], v4.x * se, v4.y * se, v4.z * se, v4.w * se);
    if ((lane & 3) == 0) atomicAdd(&g_z[d * HH + (lane >> 2)], se);
}

// ---------------- h_attn = wV / (z + 1e-6), in place on g_wV ----------------
__global__ void finalize_attn() {
    int i = blockIdx.x * 256 + threadIdx.x;  // i < NN*DD
    int n = i >> 7;
    int d = i & 127;
    g_wV[i] = g_wV[i] / (g_z[n * HH + (d >> 4)] + 1e-6f);
}

// ---------------- launch ----------------------------------------------------
extern "C" void kernel_launch(void* const* d_in, const int* in_sizes, int n_in,
                              void* d_out, int out_size) {
    const float* h = (const float*)d_in[0];
    const float* e = (const float*)d_in[1];
    const int* src = (const int*)d_in[2];
    const int* dst = (const int*)d_in[3];
    const float* WQ = (const float*)d_in[4];
    const float* WK = (const float*)d_in[5];
    const float* WV = (const float*)d_in[6];
    const float* We = (const float*)d_in[7];
    const float* WOh = (const float*)d_in[8];
    const float* bOh = (const float*)d_in[9];
    const float* WOe = (const float*)d_in[10];
    const float* bOe = (const float*)d_in[11];
    const float* g1h = (const float*)d_in[12];
    const float* b1h = (const float*)d_in[13];
    const float* g1e = (const float*)d_in[14];
    const float* b1e = (const float*)d_in[15];
    const float* Wh1 = (const float*)d_in[16];
    const float* bh1 = (const float*)d_in[17];
    const float* Wh2 = (const float*)d_in[18];
    const float* bh2 = (const float*)d_in[19];
    const float* We1 = (const float*)d_in[20];
    const float* be1 = (const float*)d_in[21];
    const float* We2 = (const float*)d_in[22];
    const float* be2 = (const float*)d_in[23];
    const float* g2h = (const float*)d_in[24];
    const float* b2h = (const float*)d_in[25];
    const float* g2e = (const float*)d_in[26];
    const float* b2e = (const float*)d_in[27];

    float* out_h = (float*)d_out;
    float* out_e = out_h + (size_t)NN * DD;

    float *pQ, *pK, *pV, *pwV, *ph1, *phh, *ppe, *pe1, *phe;
    cudaGetSymbolAddress((void**)&pQ, g_Q);
    cudaGetSymbolAddress((void**)&pK, g_K);
    cudaGetSymbolAddress((void**)&pV, g_V);
    cudaGetSymbolAddress((void**)&pwV, g_wV);
    cudaGetSymbolAddress((void**)&ph1, g_h1);
    cudaGetSymbolAddress((void**)&phh, g_hid_h);
    cudaGetSymbolAddress((void**)&ppe, g_pe);
    cudaGetSymbolAddress((void**)&pe1, g_e1);
    cudaGetSymbolAddress((void**)&phe, g_hid_e);

    const int MB_N = (NN + 127) / 128;  // 313
    const int MB_E = EE / 128;          // 5000

    zero_kernel<<<(NN * DD + NN * HH + 255) / 256, 256>>>();

    // QKV + edge projection
    gemm_tc<false, false, false><<<dim3(1, MB_N), 256>>>(h, WQ, nullptr, pQ, NN, DD, DD,
                                                         nullptr, nullptr, nullptr);
    gemm_tc<false, false, false><<<dim3(1, MB_N), 256>>>(h, WK, nullptr, pK, NN, DD, DD,
                                                         nullptr, nullptr, nullptr);
    gemm_tc<false, false, false><<<dim3(1, MB_N), 256>>>(h, WV, nullptr, pV, NN, DD, DD,
                                                         nullptr, nullptr, nullptr);
    gemm_tc<false, false, false><<<dim3(1, MB_E), 256>>>(e, We, nullptr, ppe, EE, DD, DD,
                                                         nullptr, nullptr, nullptr);

    // attention over edges
    edge_attn<<<EE / 8, 256>>>(src, dst);
    finalize_attn<<<NN * DD / 256, 256>>>();

    // output projections with fused residual+LN
    gemm_tc<false, false, true><<<dim3(1, MB_N), 256>>>(pwV, WOh, bOh, ph1, NN, DD, DD,
                                                        h, g1h, b1h);
    gemm_tc<false, false, true><<<dim3(1, MB_E), 256>>>(ppe, WOe, bOe, pe1, EE, DD, DD,
                                                        e, g1e, b1e);

    // node FFN (LN fused into second GEMM)
    gemm_tc<true, true, false><<<dim3(2, MB_N), 256>>>(ph1, Wh1, bh1, phh, NN, DD, D2,
                                                       nullptr, nullptr, nullptr);
    gemm_tc<false, false, true><<<dim3(1, MB_N), 256>>>(phh, Wh2, bh2, out_h, NN, D2, DD,
                                                        ph1, g2h, b2h);

    // edge FFN (LN fused into second GEMM)
    gemm_tc<true, true, false><<<dim3(2, MB_E), 256>>>(pe1, We1, be1, phe, EE, DD, D2,
                                                       nullptr, nullptr, nullptr);
    gemm_tc<false, false, true><<<dim3(1, MB_E), 256>>>(phe, We2, be2, out_e, EE, D2, DD,
                                                        pe1, g2e, b2e);
}

// round 8
// speedup vs baseline: 1.7108x; 1.5011x over previous
#include <cuda_runtime.h>
#include <cuda_bf16.h>
#include <math.h>

#define NN 40000
#define EE 640000
#define DD 128
#define HH 8
#define HD 16
#define D2 256
#define SA 40

typedef __nv_bfloat16 bf16;

// ---------------- scratch ----------------------------------------------------
__device__ float g_Q[NN * DD];
__device__ float g_K[NN * DD];
__device__ float g_V[NN * DD];
__device__ float g_wV[NN * DD];
__device__ float g_z[NN * HH];
__device__ float g_h1[NN * DD];
__device__ float g_e1[(size_t)EE * DD];
__device__ float g_pe[(size_t)EE * DD];

// split bf16 buffers (hi/lo)
__device__ bf16 g_hh[NN * DD];
__device__ bf16 g_hl[NN * DD];
__device__ bf16 g_eh[(size_t)EE * DD];
__device__ bf16 g_el[(size_t)EE * DD];
__device__ bf16 g_sch[(size_t)EE * DD];
__device__ bf16 g_scl[(size_t)EE * DD];
__device__ bf16 g_wvh[NN * DD];
__device__ bf16 g_wvl[NN * DD];
__device__ bf16 g_h1h[NN * DD];
__device__ bf16 g_h1l[NN * DD];
__device__ bf16 g_e1h[(size_t)EE * DD];
__device__ bf16 g_e1l[(size_t)EE * DD];
__device__ bf16 g_hidhh[NN * D2];
__device__ bf16 g_hidhl[NN * D2];
__device__ bf16 g_hideh[(size_t)EE * D2];
__device__ bf16 g_hidel[(size_t)EE * D2];
// pre-transposed split weights: Bt[n][k] at fixed offsets
#define W_TOT 229376
__device__ bf16 g_Wth[W_TOT];
__device__ bf16 g_Wtl[W_TOT];
// offsets
#define OWQ 0
#define OWK 16384
#define OWV 32768
#define OWE 49152
#define OWOH 65536
#define OWOE 81920
#define OWH1 98304
#define OWE1 131072
#define OWH2 163840
#define OWE2 196608

// ---------------- helpers ----------------------------------------------------
__device__ __forceinline__ void fsplit(float x, bf16& hi, bf16& lo) {
    hi = __float2bfloat16_rn(x);
    lo = __float2bfloat16_rn(x - __bfloat162float(hi));
}

__device__ __forceinline__ void mma16816(float* c, const unsigned* a, const unsigned* b) {
    asm volatile(
        "mma.sync.aligned.m16n8k16.row.col.f32.bf16.bf16.f32 "
        "{%0,%1,%2,%3}, {%4,%5,%6,%7}, {%8,%9}, {%0,%1,%2,%3};"
        : "+f"(c[0]), "+f"(c[1]), "+f"(c[2]), "+f"(c[3])
        : "r"(a[0]), "r"(a[1]), "r"(a[2]), "r"(a[3]), "r"(b[0]), "r"(b[1]));
}

__device__ __forceinline__ void ldsm4(unsigned& r0, unsigned& r1, unsigned& r2, unsigned& r3,
                                      const bf16* p) {
    unsigned addr = (unsigned)__cvta_generic_to_shared(p);
    asm volatile("ldmatrix.sync.aligned.m8n8.x4.shared.b16 {%0,%1,%2,%3}, [%4];"
                 : "=r"(r0), "=r"(r1), "=r"(r2), "=r"(r3)
                 : "r"(addr));
}

__device__ __forceinline__ void cpa16(unsigned saddr, const void* g, int srcsize) {
    asm volatile("cp.async.cg.shared.global [%0], [%1], 16, %2;"
                 :: "r"(saddr), "l"(g), "r"(srcsize));
}

__device__ __forceinline__ void red_add_v4(float* p, float a, float b, float c, float d) {
    asm volatile("red.global.add.v4.f32 [%0], {%1,%2,%3,%4};"
                 :: "l"(p), "f"(a), "f"(b), "f"(c), "f"(d)
                 : "memory");
}

__device__ __forceinline__ void store_split2(bf16* ph, bf16* pl, float a, float b) {
    __nv_bfloat162 hv, lv;
    bf16 h0, l0, h1, l1;
    fsplit(a, h0, l0);
    fsplit(b, h1, l1);
    hv.x = h0; hv.y = h1;
    lv.x = l0; lv.y = l1;
    *(__nv_bfloat162*)ph = hv;
    *(__nv_bfloat162*)pl = lv;
}

// ---------------- GEMM: C[M,Ncol] = A[M,K] @ Bt[Ncol,K]^T -------------------
// A, B pre-split bf16. cp.async double-buffered, BK=32, 128x128 block tile,
// 8 warps (4x2), warp tile 32x64, 3-term hi/lo MMA.
// EPI: 0 = plain fp32 C out; 1 = bias+relu, split bf16 out only;
//      2 = LN(base + C + bias)*gamma+beta -> fp32 C (+ split if SPLIT_OUT).
template <int EPI, bool SPLIT_OUT>
__global__ __launch_bounds__(256, 1) void gemm_tc(
    const bf16* __restrict__ Ah_g, const bf16* __restrict__ Al_g,
    const bf16* __restrict__ Bh_g, const bf16* __restrict__ Bl_g,
    const float* __restrict__ bias, float* __restrict__ C,
    bf16* __restrict__ Ch, bf16* __restrict__ Cl,
    int M, int K, int Ncol,
    const float* __restrict__ base, const float* __restrict__ gamma,
    const float* __restrict__ beta)
{
    extern __shared__ bf16 smem[];          // 2 stages x 4 arrays x 5120 bf16
    __shared__ float rsum[128];
    __shared__ float rsq[128];

    const int tid = threadIdx.x;
    const int lane = tid & 31;
    const int wid = tid >> 5;
    const int warp_m = wid & 3;
    const int warp_n = wid >> 2;
    const int bm = blockIdx.y * 128;
    const int bn = blockIdx.x * 128;
    const int g = lane >> 2;
    const int tg = lane & 3;

    const int arow = warp_m * 32 + (lane & 15);
    const int akoff = (lane >> 4) << 3;
    const int brow = warp_n * 64 + ((lane >> 4) & 1) * 8 + (lane & 7);
    const int bkoff = ((lane >> 3) & 1) << 3;

    const unsigned sb = (unsigned)__cvta_generic_to_shared(smem);

    float c[2][8][4];
#pragma unroll
    for (int mt = 0; mt < 2; mt++)
#pragma unroll
        for (int nt = 0; nt < 8; nt++)
#pragma unroll
            for (int j = 0; j < 4; j++) c[mt][nt][j] = 0.f;

    auto issue_tile = [&](int t) {
        const unsigned sbase = sb + (t & 1) * 40960;   // bytes
        const int k0 = t * 32;
#pragma unroll
        for (int rep = 0; rep < 2; rep++) {
            int idx = tid + rep * 256;
            int r = idx >> 2;
            int ce = (idx & 3) << 3;                   // bf16 elems
            int ar = bm + r;
            int asz = (ar < M) ? 16 : 0;
            if (ar >= M) ar = M - 1;
            size_t aoff = (size_t)ar * K + k0 + ce;
            unsigned d = sbase + (unsigned)(r * SA + ce) * 2;
            cpa16(d, Ah_g + aoff, asz);
            cpa16(d + 10240, Al_g + aoff, asz);
            size_t boff = (size_t)(bn + r) * K + k0 + ce;
            cpa16(d + 20480, Bh_g + boff, 16);
            cpa16(d + 30720, Bl_g + boff, 16);
        }
    };

    const int T = K >> 5;
    issue_tile(0);
    asm volatile("cp.async.commit_group;");

    for (int t = 0; t < T; t++) {
        if (t + 1 < T) {
            issue_tile(t + 1);
            asm volatile("cp.async.commit_group;");
            asm volatile("cp.async.wait_group 1;");
        } else {
            asm volatile("cp.async.wait_group 0;");
        }
        __syncthreads();

        const bf16* Ah_s = smem + (t & 1) * 20480;
        const bf16* Al_s = Ah_s + 5120;
        const bf16* Bh_s = Ah_s + 10240;
        const bf16* Bl_s = Ah_s + 15360;

#pragma unroll
        for (int ks = 0; ks < 32; ks += 16) {
            unsigned ah[2][4], al[2][4], bb[8][2];
#pragma unroll
            for (int mt = 0; mt < 2; mt++) {
                ldsm4(ah[mt][0], ah[mt][1], ah[mt][2], ah[mt][3],
                      &Ah_s[(arow + mt * 16) * SA + ks + akoff]);
                ldsm4(al[mt][0], al[mt][1], al[mt][2], al[mt][3],
                      &Al_s[(arow + mt * 16) * SA + ks + akoff]);
            }
#pragma unroll
            for (int j = 0; j < 4; j++)
                ldsm4(bb[2 * j][0], bb[2 * j][1], bb[2 * j + 1][0], bb[2 * j + 1][1],
                      &Bh_s[(brow + j * 16) * SA + ks + bkoff]);
#pragma unroll
            for (int nt = 0; nt < 8; nt++)
#pragma unroll
                for (int mt = 0; mt < 2; mt++) {
                    mma16816(c[mt][nt], ah[mt], bb[nt]);
                    mma16816(c[mt][nt], al[mt], bb[nt]);
                }
#pragma unroll
            for (int j = 0; j < 4; j++)
                ldsm4(bb[2 * j][0], bb[2 * j][1], bb[2 * j + 1][0], bb[2 * j + 1][1],
                      &Bl_s[(brow + j * 16) * SA + ks + bkoff]);
#pragma unroll
            for (int nt = 0; nt < 8; nt++)
#pragma unroll
                for (int mt = 0; mt < 2; mt++) mma16816(c[mt][nt], ah[mt], bb[nt]);
        }
        __syncthreads();
    }

    if (EPI == 2) {
        // fused residual + bias + LayerNorm (Ncol==128, gridDim.x==1)
        if (tid < 128) { rsum[tid] = 0.f; rsq[tid] = 0.f; }
        __syncthreads();
        float p[2][2] = {{0.f, 0.f}, {0.f, 0.f}};
        float q[2][2] = {{0.f, 0.f}, {0.f, 0.f}};
#pragma unroll
        for (int mt = 0; mt < 2; mt++) {
            int r0g = bm + warp_m * 32 + mt * 16 + g;
            int r1g = r0g + 8;
#pragma unroll
            for (int nt = 0; nt < 8; nt++) {
                int cb = warp_n * 64 + nt * 8 + tg * 2;
                float b0 = bias[cb], b1 = bias[cb + 1];
                float2 ba0 = make_float2(0.f, 0.f), ba1 = make_float2(0.f, 0.f);
                if (r0g < M) ba0 = *(const float2*)&base[(size_t)r0g * 128 + cb];
                if (r1g < M) ba1 = *(const float2*)&base[(size_t)r1g * 128 + cb];
                float v0 = c[mt][nt][0] + b0 + ba0.x;
                float v1 = c[mt][nt][1] + b1 + ba0.y;
                float v2 = c[mt][nt][2] + b0 + ba1.x;
                float v3 = c[mt][nt][3] + b1 + ba1.y;
                c[mt][nt][0] = v0; c[mt][nt][1] = v1;
                c[mt][nt][2] = v2; c[mt][nt][3] = v3;
                p[mt][0] += v0 + v1; q[mt][0] += v0 * v0 + v1 * v1;
                p[mt][1] += v2 + v3; q[mt][1] += v2 * v2 + v3 * v3;
            }
        }
#pragma unroll
        for (int o = 1; o <= 2; o <<= 1) {
#pragma unroll
            for (int mt = 0; mt < 2; mt++)
#pragma unroll
                for (int r = 0; r < 2; r++) {
                    p[mt][r] += __shfl_xor_sync(0xffffffffu, p[mt][r], o);
                    q[mt][r] += __shfl_xor_sync(0xffffffffu, q[mt][r], o);
                }
        }
        if (tg == 0) {
#pragma unroll
            for (int mt = 0; mt < 2; mt++) {
                int rl = warp_m * 32 + mt * 16 + g;
                atomicAdd(&rsum[rl], p[mt][0]);
                atomicAdd(&rsq[rl], q[mt][0]);
                atomicAdd(&rsum[rl + 8], p[mt][1]);
                atomicAdd(&rsq[rl + 8], q[mt][1]);
            }
        }
        __syncthreads();
#pragma unroll
        for (int mt = 0; mt < 2; mt++) {
            int rl0 = warp_m * 32 + mt * 16 + g;
            int rl1 = rl0 + 8;
            int r0g = bm + rl0, r1g = bm + rl1;
            float m0 = rsum[rl0] * (1.f / 128.f);
            float m1 = rsum[rl1] * (1.f / 128.f);
            float rs0 = rsqrtf(rsq[rl0] * (1.f / 128.f) - m0 * m0 + 1e-5f);
            float rs1 = rsqrtf(rsq[rl1] * (1.f / 128.f) - m1 * m1 + 1e-5f);
#pragma unroll
            for (int nt = 0; nt < 8; nt++) {
                int cb = warp_n * 64 + nt * 8 + tg * 2;
                float2 ga = *(const float2*)&gamma[cb];
                float2 be = *(const float2*)&beta[cb];
                if (r0g < M) {
                    float o0 = (c[mt][nt][0] - m0) * rs0 * ga.x + be.x;
                    float o1 = (c[mt][nt][1] - m0) * rs0 * ga.y + be.y;
                    *(float2*)&C[(size_t)r0g * 128 + cb] = make_float2(o0, o1);
                    if (SPLIT_OUT)
                        store_split2(&Ch[(size_t)r0g * 128 + cb], &Cl[(size_t)r0g * 128 + cb], o0, o1);
                }
                if (r1g < M) {
                    float o2 = (c[mt][nt][2] - m1) * rs1 * ga.x + be.x;
                    float o3 = (c[mt][nt][3] - m1) * rs1 * ga.y + be.y;
                    *(float2*)&C[(size_t)r1g * 128 + cb] = make_float2(o2, o3);
                    if (SPLIT_OUT)
                        store_split2(&Ch[(size_t)r1g * 128 + cb], &Cl[(size_t)r1g * 128 + cb], o2, o3);
                }
            }
        }
    } else {
#pragma unroll
        for (int mt = 0; mt < 2; mt++) {
#pragma unroll
            for (int nt = 0; nt < 8; nt++) {
                int r0 = bm + warp_m * 32 + mt * 16 + g;
                int r1 = r0 + 8;
                int cb = bn + warp_n * 64 + nt * 8 + tg * 2;
                float v0 = c[mt][nt][0], v1 = c[mt][nt][1];
                float v2 = c[mt][nt][2], v3 = c[mt][nt][3];
                if (EPI == 1) {
                    float b0 = bias[cb], b1 = bias[cb + 1];
                    v0 = fmaxf(v0 + b0, 0.f); v1 = fmaxf(v1 + b1, 0.f);
                    v2 = fmaxf(v2 + b0, 0.f); v3 = fmaxf(v3 + b1, 0.f);
                    if (r0 < M)
                        store_split2(&Ch[(size_t)r0 * Ncol + cb], &Cl[(size_t)r0 * Ncol + cb], v0, v1);
                    if (r1 < M)
                        store_split2(&Ch[(size_t)r1 * Ncol + cb], &Cl[(size_t)r1 * Ncol + cb], v2, v3);
                } else {
                    if (r0 < M) *(float2*)&C[(size_t)r0 * Ncol + cb] = make_float2(v0, v1);
                    if (r1 < M) *(float2*)&C[(size_t)r1 * Ncol + cb] = make_float2(v2, v3);
                }
            }
        }
    }
}

// ---------------- conversions ------------------------------------------------
__global__ void conv_split(const float* __restrict__ in, bf16* __restrict__ oh,
                           bf16* __restrict__ ol, int n4) {
    int i = blockIdx.x * 256 + threadIdx.x;
    if (i >= n4) return;
    float4 v = ((const float4*)in)[i];
    bf16 hs[4], ls[4];
    fsplit(v.x, hs[0], ls[0]);
    fsplit(v.y, hs[1], ls[1]);
    fsplit(v.z, hs[2], ls[2]);
    fsplit(v.w, hs[3], ls[3]);
    ((uint2*)oh)[i] = *(uint2*)hs;
    ((uint2*)ol)[i] = *(uint2*)ls;
}

__global__ void conv_weights(const float* WQ, const float* WK, const float* WV,
                             const float* We, const float* WOh, const float* WOe,
                             const float* Wh1, const float* Wh2,
                             const float* We1, const float* We2) {
    int idx = blockIdx.x * 256 + threadIdx.x;
    if (idx >= W_TOT) return;
    const float* src;
    int Kd, Nd, off, s;
    if (idx < 98304) {
        int seg = idx / 16384;
        s = idx - seg * 16384;
        const float* tab[6] = {WQ, WK, WV, We, WOh, WOe};
        src = tab[seg]; Kd = 128; Nd = 128; off = seg * 16384;
    } else if (idx < 131072) { s = idx - 98304;  src = Wh1; Kd = 128; Nd = 256; off = OWH1; }
    else if (idx < 163840)   { s = idx - 131072; src = We1; Kd = 128; Nd = 256; off = OWE1; }
    else if (idx < 196608)   { s = idx - 163840; src = Wh2; Kd = 256; Nd = 128; off = OWH2; }
    else                     { s = idx - 196608; src = We2; Kd = 256; Nd = 128; off = OWE2; }
    int k = s / Nd, n = s - k * Nd;
    bf16 hi, lo;
    fsplit(src[s], hi, lo);
    g_Wth[off + n * Kd + k] = hi;
    g_Wtl[off + n * Kd + k] = lo;
}

// ---------------- zero wV / z ------------------------------------------------
__global__ void zero_kernel() {
    int i = blockIdx.x * 256 + threadIdx.x;
    if (i < NN * DD) g_wV[i] = 0.f;
    int j = i - NN * DD;
    if (j >= 0 && j < NN * HH) g_z[j] = 0.f;
}

// ---------------- edge attention --------------------------------------------
__global__ void edge_attn(const int* __restrict__ src, const int* __restrict__ dst) {
    int e = blockIdx.x * 8 + (threadIdx.x >> 5);
    if (e >= EE) return;
    int lane = threadIdx.x & 31;
    int s = src[e];
    int d = dst[e];
    int col = lane * 4;
    size_t eb = (size_t)e * DD + col;

    float4 k4 = *(const float4*)&g_K[(size_t)s * DD + col];
    float4 q4 = *(const float4*)&g_Q[(size_t)d * DD + col];
    float4 p4 = *(const float4*)&g_pe[eb];
    float4 v4 = *(const float4*)&g_V[(size_t)s * DD + col];

    const float isq = 0.25f;
    float4 sc;
    sc.x = k4.x * q4.x * isq * p4.x;
    sc.y = k4.y * q4.y * isq * p4.y;
    sc.z = k4.z * q4.z * isq * p4.z;
    sc.w = k4.w * q4.w * isq * p4.w;

    // score (e_out) written directly as split bf16 (GEMM A operand only)
    bf16 hs[4], ls[4];
    fsplit(sc.x, hs[0], ls[0]);
    fsplit(sc.y, hs[1], ls[1]);
    fsplit(sc.z, hs[2], ls[2]);
    fsplit(sc.w, hs[3], ls[3]);
    *(uint2*)&g_sch[eb] = *(uint2*)hs;
    *(uint2*)&g_scl[eb] = *(uint2*)ls;

    float part = sc.x + sc.y + sc.z + sc.w;
    part += __shfl_xor_sync(0xffffffffu, part, 1);
    part += __shfl_xor_sync(0xffffffffu, part, 2);

    float se = expf(fminf(fmaxf(part, -5.f), 5.f));

    red_add_v4(&g_wV[(size_t)d * DD + col], v4.x * se, v4.y * se, v4.z * se, v4.w * se);
    if ((lane & 3) == 0) atomicAdd(&g_z[d * HH + (lane >> 2)], se);
}

// ---------------- h_attn = wV/(z+eps) -> split bf16 --------------------------
__global__ void finalize_attn() {
    int i = blockIdx.x * 256 + threadIdx.x;   // i < NN*DD/4
    if (i >= NN * DD / 4) return;
    int base = i * 4;
    int n = base >> 7;
    int col = base & 127;
    float inv = 1.f / (g_z[n * HH + (col >> 4)] + 1e-6f);
    float4 w = ((const float4*)g_wV)[i];
    bf16 hs[4], ls[4];
    fsplit(w.x * inv, hs[0], ls[0]);
    fsplit(w.y * inv, hs[1], ls[1]);
    fsplit(w.z * inv, hs[2], ls[2]);
    fsplit(w.w * inv, hs[3], ls[3]);
    ((uint2*)g_wvh)[i] = *(uint2*)hs;
    ((uint2*)g_wvl)[i] = *(uint2*)ls;
}

// ---------------- launch ------------------------------------------------------
#define SMEM_BYTES 81920

extern "C" void kernel_launch(void* const* d_in, const int* in_sizes, int n_in,
                              void* d_out, int out_size) {
    const float* h = (const float*)d_in[0];
    const float* e = (const float*)d_in[1];
    const int* src = (const int*)d_in[2];
    const int* dst = (const int*)d_in[3];
    const float* WQ = (const float*)d_in[4];
    const float* WK = (const float*)d_in[5];
    const float* WV = (const float*)d_in[6];
    const float* We = (const float*)d_in[7];
    const float* WOh = (const float*)d_in[8];
    const float* bOh = (const float*)d_in[9];
    const float* WOe = (const float*)d_in[10];
    const float* bOe = (const float*)d_in[11];
    const float* g1h = (const float*)d_in[12];
    const float* b1h = (const float*)d_in[13];
    const float* g1e = (const float*)d_in[14];
    const float* b1e = (const float*)d_in[15];
    const float* Wh1 = (const float*)d_in[16];
    const float* bh1 = (const float*)d_in[17];
    const float* Wh2 = (const float*)d_in[18];
    const float* bh2 = (const float*)d_in[19];
    const float* We1 = (const float*)d_in[20];
    const float* be1 = (const float*)d_in[21];
    const float* We2 = (const float*)d_in[22];
    const float* be2 = (const float*)d_in[23];
    const float* g2h = (const float*)d_in[24];
    const float* b2h = (const float*)d_in[25];
    const float* g2e = (const float*)d_in[26];
    const float* b2e = (const float*)d_in[27];

    float* out_h = (float*)d_out;
    float* out_e = out_h + (size_t)NN * DD;

    cudaFuncSetAttribute(gemm_tc<0, false>, cudaFuncAttributeMaxDynamicSharedMemorySize, SMEM_BYTES);
    cudaFuncSetAttribute(gemm_tc<1, true>, cudaFuncAttributeMaxDynamicSharedMemorySize, SMEM_BYTES);
    cudaFuncSetAttribute(gemm_tc<2, true>, cudaFuncAttributeMaxDynamicSharedMemorySize, SMEM_BYTES);
    cudaFuncSetAttribute(gemm_tc<2, false>, cudaFuncAttributeMaxDynamicSharedMemorySize, SMEM_BYTES);

    float *pQ, *pK, *pV, *pwV, *ph1, *pe1, *ppe;
    bf16 *phh, *phl, *peh, *pel, *psch, *pscl, *pwvh, *pwvl;
    bf16 *ph1h, *ph1l, *pe1h, *pe1l, *phidhh, *phidhl, *phideh, *phidel;
    bf16 *pWth, *pWtl;
    cudaGetSymbolAddress((void**)&pQ, g_Q);
    cudaGetSymbolAddress((void**)&pK, g_K);
    cudaGetSymbolAddress((void**)&pV, g_V);
    cudaGetSymbolAddress((void**)&pwV, g_wV);
    cudaGetSymbolAddress((void**)&ph1, g_h1);
    cudaGetSymbolAddress((void**)&pe1, g_e1);
    cudaGetSymbolAddress((void**)&ppe, g_pe);
    cudaGetSymbolAddress((void**)&phh, g_hh);
    cudaGetSymbolAddress((void**)&phl, g_hl);
    cudaGetSymbolAddress((void**)&peh, g_eh);
    cudaGetSymbolAddress((void**)&pel, g_el);
    cudaGetSymbolAddress((void**)&psch, g_sch);
    cudaGetSymbolAddress((void**)&pscl, g_scl);
    cudaGetSymbolAddress((void**)&pwvh, g_wvh);
    cudaGetSymbolAddress((void**)&pwvl, g_wvl);
    cudaGetSymbolAddress((void**)&ph1h, g_h1h);
    cudaGetSymbolAddress((void**)&ph1l, g_h1l);
    cudaGetSymbolAddress((void**)&pe1h, g_e1h);
    cudaGetSymbolAddress((void**)&pe1l, g_e1l);
    cudaGetSymbolAddress((void**)&phidhh, g_hidhh);
    cudaGetSymbolAddress((void**)&phidhl, g_hidhl);
    cudaGetSymbolAddress((void**)&phideh, g_hideh);
    cudaGetSymbolAddress((void**)&phidel, g_hidel);
    cudaGetSymbolAddress((void**)&pWth, g_Wth);
    cudaGetSymbolAddress((void**)&pWtl, g_Wtl);

    const int MB_N = (NN + 127) / 128;  // 313
    const int MB_E = EE / 128;          // 5000

    // prep: weights + inputs split, zero accumulators
    conv_weights<<<(W_TOT + 255) / 256, 256>>>(WQ, WK, WV, We, WOh, WOe, Wh1, Wh2, We1, We2);
    conv_split<<<(NN * DD / 4 + 255) / 256, 256>>>(h, phh, phl, NN * DD / 4);
    conv_split<<<(EE * DD / 4 + 255) / 256, 256>>>(e, peh, pel, EE * DD / 4);
    zero_kernel<<<(NN * DD + NN * HH + 255) / 256, 256>>>();

    // QKV + edge projection
    gemm_tc<0, false><<<dim3(1, MB_N), 256, SMEM_BYTES>>>(
        phh, phl, pWth + OWQ, pWtl + OWQ, nullptr, pQ, nullptr, nullptr,
        NN, DD, DD, nullptr, nullptr, nullptr);
    gemm_tc<0, false><<<dim3(1, MB_N), 256, SMEM_BYTES>>>(
        phh, phl, pWth + OWK, pWtl + OWK, nullptr, pK, nullptr, nullptr,
        NN, DD, DD, nullptr, nullptr, nullptr);
    gemm_tc<0, false><<<dim3(1, MB_N), 256, SMEM_BYTES>>>(
        phh, phl, pWth + OWV, pWtl + OWV, nullptr, pV, nullptr, nullptr,
        NN, DD, DD, nullptr, nullptr, nullptr);
    gemm_tc<0, false><<<dim3(1, MB_E), 256, SMEM_BYTES>>>(
        peh, pel, pWth + OWE, pWtl + OWE, nullptr, ppe, nullptr, nullptr,
        EE, DD, DD, nullptr, nullptr, nullptr);

    // attention
    edge_attn<<<EE / 8, 256>>>(src, dst);
    finalize_attn<<<(NN * DD / 4 + 255) / 256, 256>>>();

    // output projections with fused residual + LN (also emit split for FFN)
    gemm_tc<2, true><<<dim3(1, MB_N), 256, SMEM_BYTES>>>(
        pwvh, pwvl, pWth + OWOH, pWtl + OWOH, bOh, ph1, ph1h, ph1l,
        NN, DD, DD, h, g1h, b1h);
    gemm_tc<2, true><<<dim3(1, MB_E), 256, SMEM_BYTES>>>(
        psch, pscl, pWth + OWOE, pWtl + OWOE, bOe, pe1, pe1h, pe1l,
        EE, DD, DD, e, g1e, b1e);

    // node FFN
    gemm_tc<1, true><<<dim3(2, MB_N), 256, SMEM_BYTES>>>(
        ph1h, ph1l, pWth + OWH1, pWtl + OWH1, bh1, nullptr, phidhh, phidhl,
        NN, DD, D2, nullptr, nullptr, nullptr);
    gemm_tc<2, false><<<dim3(1, MB_N), 256, SMEM_BYTES>>>(
        phidhh, phidhl, pWth + OWH2, pWtl + OWH2, bh2, out_h, nullptr, nullptr,
        NN, D2, DD, ph1, g2h, b2h);

    // edge FFN
    gemm_tc<1, true><<<dim3(2, MB_E), 256, SMEM_BYTES>>>(
        pe1h, pe1l, pWth + OWE1, pWtl + OWE1, be1, nullptr, phideh, phidel,
        EE, DD, D2, nullptr, nullptr, nullptr);
    gemm_tc<2, false><<<dim3(1, MB_E), 256, SMEM_BYTES>>>(
        phideh, phidel, pWth + OWE2, pWtl + OWE2, be2, out_e, nullptr, nullptr,
        EE, D2, DD, pe1, g2e, b2e);
}